// round 16
// baseline (speedup 1.0000x reference)
#include <cuda_runtime.h>
#include <cuda_bf16.h>
#include <float.h>
#include <math.h>
#include <stdint.h>

#define S_ROWS 2048
#define T_ROWS 50000
#define DDIM   1024
#define KNN    4
#define BM     128
#define BN     128
#define BKS    128                      // k per stage (128B fp8 rows)
#define NSTG   (DDIM / BKS)             // 8
#define MT     (S_ROWS / BM)            // 16
#define NT     ((T_ROWS + BN - 1) / BN) // 391
#define RESC   12

#define STAGE_BYTES (BM * 128 + BN * 128)            // 32KB
#define SMEM_BYTES  (3 * STAGE_BYTES)                 // 98304 (> sims 128*132*4)

// ---------------- device scratch ----------------
__device__ uint8_t g_src8[S_ROWS * DDIM];              // e4m3, x4
__device__ uint8_t g_tgt8[(size_t)T_ROWS * DDIM];      // e4m3, normalized, x64
__device__ float g_invn[T_ROWS];
__device__ float2 g_pc[S_ROWS * NT * KNN];             // packed (val, idx-bits)

// ---------------- helpers ----------------
__device__ __forceinline__ uint32_t smem_to_u32(const void* p) {
    uint32_t a;
    asm("{ .reg .u64 t; cvta.to.shared.u64 t, %1; cvt.u32.u64 %0, t; }" : "=r"(a) : "l"(p));
    return a;
}
__device__ __forceinline__ void cp_async16(uint32_t dst, const void* src, uint32_t src_bytes) {
    asm volatile("cp.async.cg.shared.global [%0], [%1], 16, %2;\n"
                 :: "r"(dst), "l"(src), "r"(src_bytes) : "memory");
}
__device__ __forceinline__ void cp_commit() {
    asm volatile("cp.async.commit_group;\n" ::: "memory");
}
template <int N>
__device__ __forceinline__ void cp_wait() {
    asm volatile("cp.async.wait_group %0;\n" :: "n"(N) : "memory");
}
__device__ __forceinline__ void ldsm_x4(uint32_t addr, uint32_t& r0, uint32_t& r1,
                                        uint32_t& r2, uint32_t& r3) {
    asm volatile("ldmatrix.sync.aligned.m8n8.x4.shared.b16 {%0,%1,%2,%3}, [%4];\n"
                 : "=r"(r0), "=r"(r1), "=r"(r2), "=r"(r3) : "r"(addr));
}
__device__ __forceinline__ void mma_fp8(float& c0, float& c1, float& c2, float& c3,
                                        uint32_t a0, uint32_t a1, uint32_t a2, uint32_t a3,
                                        uint32_t b0, uint32_t b1) {
    asm volatile("mma.sync.aligned.m16n8k32.row.col.f32.e4m3.e4m3.f32 "
                 "{%0,%1,%2,%3}, {%4,%5,%6,%7}, {%8,%9}, {%0,%1,%2,%3};\n"
                 : "+f"(c0), "+f"(c1), "+f"(c2), "+f"(c3)
                 : "r"(a0), "r"(a1), "r"(a2), "r"(a3), "r"(b0), "r"(b1));
}

__device__ __forceinline__ bool better(float v, int i, float v2, int i2) {
    return (v > v2) || (v == v2 && i < i2);
}
template <int L>
__device__ __forceinline__ void insL(float v, int i, float* tv, int* ti) {
    if (!better(v, i, tv[L - 1], ti[L - 1])) return;
    tv[L - 1] = v; ti[L - 1] = i;
#pragma unroll
    for (int q = L - 1; q > 0; --q) {
        if (better(tv[q], ti[q], tv[q - 1], ti[q - 1])) {
            float fv = tv[q]; tv[q] = tv[q - 1]; tv[q - 1] = fv;
            int fi = ti[q]; ti[q] = ti[q - 1]; ti[q - 1] = fi;
        }
    }
}
__device__ __forceinline__ uint32_t pack_e4m3x4(float f0, float f1, float f2, float f3) {
    uint16_t lo, hi;
    asm("cvt.rn.satfinite.e4m3x2.f32 %0, %1, %2;" : "=h"(lo) : "f"(f1), "f"(f0));
    asm("cvt.rn.satfinite.e4m3x2.f32 %0, %1, %2;" : "=h"(hi) : "f"(f3), "f"(f2));
    return ((uint32_t)hi << 16) | lo;
}

// ---------------------------------------------------------------------------
// Kernel 1 (fused): blocks [0, T_ROWS) do target prep; [T_ROWS, +S_ROWS) src prep
// ---------------------------------------------------------------------------
__global__ void prep_kernel(const float* __restrict__ Bt, const float* __restrict__ A) {
    const int b = blockIdx.x, tid = threadIdx.x;
    if (b < T_ROWS) {
        const float4* row = reinterpret_cast<const float4*>(Bt + (size_t)b * DDIM);
        float4 v0 = row[tid * 2], v1 = row[tid * 2 + 1];
        float s = v0.x * v0.x + v0.y * v0.y + v0.z * v0.z + v0.w * v0.w +
                  v1.x * v1.x + v1.y * v1.y + v1.z * v1.z + v1.w * v1.w;
#pragma unroll
        for (int o = 16; o > 0; o >>= 1) s += __shfl_down_sync(0xffffffffu, s, o);
        __shared__ float ws[4];
        __shared__ float s_inv;
        int lane = tid & 31, w = tid >> 5;
        if (lane == 0) ws[w] = s;
        __syncthreads();
        if (tid == 0) {
            float inv = 1.f / fmaxf(sqrtf(ws[0] + ws[1] + ws[2] + ws[3]), 1e-8f);
            g_invn[b] = inv;
            s_inv = inv;
        }
        __syncthreads();
        const float q = s_inv * 64.f;
        uint2 o8;
        o8.x = pack_e4m3x4(v0.x * q, v0.y * q, v0.z * q, v0.w * q);
        o8.y = pack_e4m3x4(v1.x * q, v1.y * q, v1.z * q, v1.w * q);
        *reinterpret_cast<uint2*>(g_tgt8 + (size_t)b * DDIM + tid * 8) = o8;
    } else {
        const int t = b - T_ROWS;
        const float4* row = reinterpret_cast<const float4*>(A + (size_t)t * DDIM);
        float4 v0 = row[tid * 2], v1 = row[tid * 2 + 1];
        uint2 o8;
        o8.x = pack_e4m3x4(v0.x * 4.f, v0.y * 4.f, v0.z * 4.f, v0.w * 4.f);
        o8.y = pack_e4m3x4(v1.x * 4.f, v1.y * 4.f, v1.z * 4.f, v1.w * 4.f);
        *reinterpret_cast<uint2*>(g_src8 + (size_t)t * DDIM + tid * 8) = o8;
    }
}

// ---------------------------------------------------------------------------
// Kernel 2: coarse e4m3 GEMM (128x128 per CTA, warp tile 32x64, K=1024)
//           + fused per-row top-4 (2 threads/row, float4 scan, shfl merge)
// ---------------------------------------------------------------------------
__global__ __launch_bounds__(256, 2)
void coarse_gemm_topk() {
    extern __shared__ char smem[];
    const uint32_t sb = smem_to_u32(smem);
    const int tid = threadIdx.x;
    const int lane = tid & 31;
    const int w = tid >> 5;
    const int wm = w >> 1;          // 0..3
    const int wn = w & 1;           // 0..1
    const int m0 = blockIdx.x * BM;
    const int n0 = blockIdx.y * BN;

    const int lrow = tid >> 1;                  // 0..127
    const int lc0  = (tid & 1) << 2;            // 0 or 4
    const uint8_t* Ag = g_src8 + (size_t)(m0 + lrow) * DDIM + lc0 * 16;
    const int tr = n0 + lrow;
    const uint8_t* Bg = g_tgt8 + (size_t)min(tr, T_ROWS - 1) * DDIM + lc0 * 16;
    const uint32_t bsz = (tr < T_ROWS) ? 16u : 0u;
    uint32_t awoff[4], bwoff[4];
#pragma unroll
    for (int i = 0; i < 4; ++i) {
        int c = lc0 + i;
        awoff[i] = (uint32_t)(lrow * 128 + ((c ^ (lrow & 7)) << 4));
        bwoff[i] = (uint32_t)(BM * 128 + lrow * 128 + ((c ^ (lrow & 7)) << 4));
    }

    float acc[2][8][4];
#pragma unroll
    for (int mi = 0; mi < 2; ++mi)
#pragma unroll
        for (int ni = 0; ni < 8; ++ni)
#pragma unroll
            for (int q = 0; q < 4; ++q) acc[mi][ni][q] = 0.f;

    const int lrow8 = (lane & 7) + ((lane >> 3) & 1) * 8;
    const int khalf = (lane >> 4) & 1;
    int arowA[2], browB[4];
#pragma unroll
    for (int mi = 0; mi < 2; ++mi) arowA[mi] = wm * 32 + mi * 16 + lrow8;
#pragma unroll
    for (int nj = 0; nj < 4; ++nj) browB[nj] = wn * 64 + nj * 16 + lrow8;

#pragma unroll
    for (int s = 0; s < 2; ++s) {
        const uint32_t bbuf = sb + s * STAGE_BYTES;
#pragma unroll
        for (int i = 0; i < 4; ++i) {
            cp_async16(bbuf + awoff[i], Ag + s * BKS + i * 16, 16u);
            cp_async16(bbuf + bwoff[i], Bg + s * BKS + i * 16, bsz);
        }
        cp_commit();
    }

#pragma unroll 1
    for (int s = 0; s < NSTG; ++s) {
        if (s + 2 < NSTG) {
            const uint32_t nb = sb + ((s + 2) % 3) * STAGE_BYTES;
            const int ko = (s + 2) * BKS;
#pragma unroll
            for (int i = 0; i < 4; ++i) {
                cp_async16(nb + awoff[i], Ag + ko + i * 16, 16u);
                cp_async16(nb + bwoff[i], Bg + ko + i * 16, bsz);
            }
        }
        cp_commit();
        cp_wait<2>();
        __syncthreads();

        const uint32_t ab = sb + (s % 3) * STAGE_BYTES;
        const uint32_t bb = ab + BM * 128;
#pragma unroll
        for (int kk = 0; kk < 4; ++kk) {
            const int kc = kk * 2 + khalf;
            uint32_t a[2][4];
#pragma unroll
            for (int mi = 0; mi < 2; ++mi) {
                int r = arowA[mi];
                ldsm_x4(ab + r * 128 + ((kc ^ (r & 7)) << 4),
                        a[mi][0], a[mi][1], a[mi][2], a[mi][3]);
            }
#pragma unroll
            for (int nj = 0; nj < 4; ++nj) {
                int r = browB[nj];
                uint32_t b0, b1, b2, b3;
                ldsm_x4(bb + r * 128 + ((kc ^ (r & 7)) << 4), b0, b1, b2, b3);
#pragma unroll
                for (int mi = 0; mi < 2; ++mi) {
                    mma_fp8(acc[mi][nj * 2][0], acc[mi][nj * 2][1],
                            acc[mi][nj * 2][2], acc[mi][nj * 2][3],
                            a[mi][0], a[mi][1], a[mi][2], a[mi][3], b0, b2);
                    mma_fp8(acc[mi][nj * 2 + 1][0], acc[mi][nj * 2 + 1][1],
                            acc[mi][nj * 2 + 1][2], acc[mi][nj * 2 + 1][3],
                            a[mi][0], a[mi][1], a[mi][2], a[mi][3], b1, b3);
                }
            }
        }
        __syncthreads();
    }

    // ---- epilogue: fragments -> smem sims [128][132]
    float* sims = reinterpret_cast<float*>(smem);
#pragma unroll
    for (int mi = 0; mi < 2; ++mi) {
        const int r = wm * 32 + mi * 16 + (lane >> 2);
#pragma unroll
        for (int ni = 0; ni < 8; ++ni) {
            const int c = wn * 64 + ni * 8 + (lane & 3) * 2;
            *reinterpret_cast<float2*>(sims + r * 132 + c) =
                make_float2(acc[mi][ni][0], acc[mi][ni][1]);
            *reinterpret_cast<float2*>(sims + (r + 8) * 132 + c) =
                make_float2(acc[mi][ni][2], acc[mi][ni][3]);
        }
    }
    __syncthreads();

    // per-row top-4: 2 threads/row, float4 vectorized scan, snapshot shfl merge
    {
        const int row  = tid >> 1;
        const int half = tid & 1;
        const int nmax = min(BN, T_ROWS - n0);   // multiple of 4 (80 on last tile)
        float tv[KNN] = {-FLT_MAX, -FLT_MAX, -FLT_MAX, -FLT_MAX};
        int   ti4[KNN] = {0x7fffffff, 0x7fffffff, 0x7fffffff, 0x7fffffff};
        const float* rowp = sims + row * 132;
        const int c0 = half * 64;
        const int c1 = min(c0 + 64, nmax);
        for (int c = c0; c < c1; c += 4) {
            const float4 v = *reinterpret_cast<const float4*>(rowp + c);
            insL<KNN>(v.x, n0 + c,     tv, ti4);
            insL<KNN>(v.y, n0 + c + 1, tv, ti4);
            insL<KNN>(v.z, n0 + c + 2, tv, ti4);
            insL<KNN>(v.w, n0 + c + 3, tv, ti4);
        }
        // snapshot partner's ORIGINAL list, then insert
        float pv[KNN]; int pi[KNN];
#pragma unroll
        for (int q = 0; q < KNN; ++q) {
            pv[q] = __shfl_xor_sync(0xffffffffu, tv[q], 1);
            pi[q] = __shfl_xor_sync(0xffffffffu, ti4[q], 1);
        }
#pragma unroll
        for (int q = 0; q < KNN; ++q) insL<KNN>(pv[q], pi[q], tv, ti4);
        if (half == 0) {
            const int m = m0 + row;
            const int base = (m * NT + blockIdx.y) * KNN;
#pragma unroll
            for (int q = 0; q < KNN; ++q)
                g_pc[base + q] = make_float2(tv[q], __int_as_float(ti4[q]));
        }
    }
}

// ---------------------------------------------------------------------------
// Kernel 3: merge -> coarse top-12 -> warp-parallel EXACT fp32 rescore
//           (8 warps, <=2 candidates each) -> top-4 -> mean
// ---------------------------------------------------------------------------
__global__ __launch_bounds__(256)
void merge_rescore_kernel(const float* __restrict__ A, const float* __restrict__ Bt,
                          float* __restrict__ out) {
    const int s = blockIdx.x;
    const int tid = threadIdx.x;
    const int lane = tid & 31, warp = tid >> 5;
    const int C = NT * KNN;   // 1564

    __shared__ float sv[256 * KNN];
    __shared__ int   si[256 * KNN];
    __shared__ int   fiR[RESC];
    __shared__ float cv[RESC];
    __shared__ int   fidx[KNN];

    // phase 1: per-thread strided top-4 (packed float2 loads)
    {
        float tv[KNN] = {-FLT_MAX, -FLT_MAX, -FLT_MAX, -FLT_MAX};
        int   ti4[KNN] = {0x7fffffff, 0x7fffffff, 0x7fffffff, 0x7fffffff};
        const int base = s * C;
        for (int c = tid; c < C; c += 256) {
            const float2 pc = g_pc[base + c];
            insL<KNN>(pc.x, __float_as_int(pc.y), tv, ti4);
        }
#pragma unroll
        for (int q = 0; q < KNN; ++q) { sv[tid * KNN + q] = tv[q]; si[tid * KNN + q] = ti4[q]; }
    }
    __syncthreads();

    // phase 2: single-thread merge -> coarse top-RESC
    if (tid == 0) {
        float fv[RESC]; int fii[RESC];
#pragma unroll
        for (int q = 0; q < RESC; ++q) { fv[q] = -FLT_MAX; fii[q] = 0x7fffffff; }
        for (int c = 0; c < 256 * KNN; ++c) insL<RESC>(sv[c], si[c], fv, fii);
#pragma unroll
        for (int q = 0; q < RESC; ++q) fiR[q] = fii[q];
    }
    __syncthreads();

    // phase 3: warp-parallel EXACT fp32 rescore (warp w -> candidates w, w+8)
    {
        const float4* ap = reinterpret_cast<const float4*>(A + (size_t)s * DDIM);
#pragma unroll
        for (int rep = 0; rep < 2; ++rep) {
            const int ci = warp + rep * 8;
            if (ci < RESC) {
                const int idx = fiR[ci];
                const float4* tp = reinterpret_cast<const float4*>(Bt + (size_t)idx * DDIM);
                float acc = 0.f;
#pragma unroll
                for (int j = 0; j < 8; ++j) {
                    const float4 s4 = ap[j * 32 + lane];
                    const float4 t4 = tp[j * 32 + lane];
                    acc = fmaf(s4.x, t4.x, acc);
                    acc = fmaf(s4.y, t4.y, acc);
                    acc = fmaf(s4.z, t4.z, acc);
                    acc = fmaf(s4.w, t4.w, acc);
                }
#pragma unroll
                for (int o = 16; o > 0; o >>= 1) acc += __shfl_down_sync(0xffffffffu, acc, o);
                if (lane == 0) cv[ci] = acc * g_invn[idx];
            }
        }
    }
    __syncthreads();

    // phase 4: final exact top-4
    if (tid == 0) {
        float fv[KNN] = {-FLT_MAX, -FLT_MAX, -FLT_MAX, -FLT_MAX};
        int   fii[KNN] = {0x7fffffff, 0x7fffffff, 0x7fffffff, 0x7fffffff};
#pragma unroll
        for (int q = 0; q < RESC; ++q) insL<KNN>(cv[q], fiR[q], fv, fii);
#pragma unroll
        for (int q = 0; q < KNN; ++q) fidx[q] = fii[q];
    }
    __syncthreads();

    // phase 5: gather 4 fp32 target rows, mean
    const float4 a = reinterpret_cast<const float4*>(Bt + (size_t)fidx[0] * DDIM)[tid];
    const float4 b = reinterpret_cast<const float4*>(Bt + (size_t)fidx[1] * DDIM)[tid];
    const float4 c = reinterpret_cast<const float4*>(Bt + (size_t)fidx[2] * DDIM)[tid];
    const float4 d = reinterpret_cast<const float4*>(Bt + (size_t)fidx[3] * DDIM)[tid];
    float4 r;
    r.x = (a.x + b.x + c.x + d.x) * 0.25f;
    r.y = (a.y + b.y + c.y + d.y) * 0.25f;
    r.z = (a.z + b.z + c.z + d.z) * 0.25f;
    r.w = (a.w + b.w + c.w + d.w) * 0.25f;
    reinterpret_cast<float4*>(out + (size_t)s * DDIM)[tid] = r;
}

// ---------------------------------------------------------------------------
extern "C" void kernel_launch(void* const* d_in, const int* in_sizes, int n_in,
                              void* d_out, int out_size) {
    const float* src = (const float*)d_in[0];   // [2048, 1024]
    const float* tgt = (const float*)d_in[1];   // [50000, 1024]
    float* out = (float*)d_out;                 // [2048, 1024]

    cudaFuncSetAttribute(coarse_gemm_topk,
                         cudaFuncAttributeMaxDynamicSharedMemorySize, SMEM_BYTES);

    prep_kernel<<<T_ROWS + S_ROWS, 128>>>(tgt, src);
    coarse_gemm_topk<<<dim3(MT, NT), 256, SMEM_BYTES>>>();
    merge_rescore_kernel<<<S_ROWS, 256>>>(src, tgt, out);
}

// round 17
// speedup vs baseline: 1.0710x; 1.0710x over previous
#include <cuda_runtime.h>
#include <cuda_bf16.h>
#include <float.h>
#include <math.h>
#include <stdint.h>

#define S_ROWS 2048
#define T_ROWS 50000
#define DDIM   1024
#define KNN    4
#define BM     128
#define BN     128
#define BKS    128                      // k per stage (128B fp8 rows)
#define NSTG   (DDIM / BKS)             // 8
#define MT     (S_ROWS / BM)            // 16
#define NT     ((T_ROWS + BN - 1) / BN) // 391
#define RESC   12

#define STAGE_BYTES (BM * 128 + BN * 128)            // 32KB
#define SMEM_BYTES  (3 * STAGE_BYTES)                 // 98304 (> sims 128*132*4)

// ---------------- device scratch ----------------
__device__ uint8_t g_src8[S_ROWS * DDIM];              // e4m3, x4
__device__ uint8_t g_tgt8[(size_t)T_ROWS * DDIM];      // e4m3, normalized, x64
__device__ float g_invn[T_ROWS];
__device__ float2 g_pc[S_ROWS * NT * KNN];             // packed (val, idx-bits)

// ---------------- helpers ----------------
__device__ __forceinline__ uint32_t smem_to_u32(const void* p) {
    uint32_t a;
    asm("{ .reg .u64 t; cvta.to.shared.u64 t, %1; cvt.u32.u64 %0, t; }" : "=r"(a) : "l"(p));
    return a;
}
__device__ __forceinline__ void cp_async16(uint32_t dst, const void* src, uint32_t src_bytes) {
    asm volatile("cp.async.cg.shared.global [%0], [%1], 16, %2;\n"
                 :: "r"(dst), "l"(src), "r"(src_bytes) : "memory");
}
__device__ __forceinline__ void cp_commit() {
    asm volatile("cp.async.commit_group;\n" ::: "memory");
}
template <int N>
__device__ __forceinline__ void cp_wait() {
    asm volatile("cp.async.wait_group %0;\n" :: "n"(N) : "memory");
}
__device__ __forceinline__ void ldsm_x4(uint32_t addr, uint32_t& r0, uint32_t& r1,
                                        uint32_t& r2, uint32_t& r3) {
    asm volatile("ldmatrix.sync.aligned.m8n8.x4.shared.b16 {%0,%1,%2,%3}, [%4];\n"
                 : "=r"(r0), "=r"(r1), "=r"(r2), "=r"(r3) : "r"(addr));
}
__device__ __forceinline__ void mma_fp8(float& c0, float& c1, float& c2, float& c3,
                                        uint32_t a0, uint32_t a1, uint32_t a2, uint32_t a3,
                                        uint32_t b0, uint32_t b1) {
    asm volatile("mma.sync.aligned.m16n8k32.row.col.f32.e4m3.e4m3.f32 "
                 "{%0,%1,%2,%3}, {%4,%5,%6,%7}, {%8,%9}, {%0,%1,%2,%3};\n"
                 : "+f"(c0), "+f"(c1), "+f"(c2), "+f"(c3)
                 : "r"(a0), "r"(a1), "r"(a2), "r"(a3), "r"(b0), "r"(b1));
}

__device__ __forceinline__ bool better(float v, int i, float v2, int i2) {
    return (v > v2) || (v == v2 && i < i2);
}
template <int L>
__device__ __forceinline__ void insL(float v, int i, float* tv, int* ti) {
    if (!better(v, i, tv[L - 1], ti[L - 1])) return;
    tv[L - 1] = v; ti[L - 1] = i;
#pragma unroll
    for (int q = L - 1; q > 0; --q) {
        if (better(tv[q], ti[q], tv[q - 1], ti[q - 1])) {
            float fv = tv[q]; tv[q] = tv[q - 1]; tv[q - 1] = fv;
            int fi = ti[q]; ti[q] = ti[q - 1]; ti[q - 1] = fi;
        }
    }
}
__device__ __forceinline__ uint32_t pack_e4m3x4(float f0, float f1, float f2, float f3) {
    uint16_t lo, hi;
    asm("cvt.rn.satfinite.e4m3x2.f32 %0, %1, %2;" : "=h"(lo) : "f"(f1), "f"(f0));
    asm("cvt.rn.satfinite.e4m3x2.f32 %0, %1, %2;" : "=h"(hi) : "f"(f3), "f"(f2));
    return ((uint32_t)hi << 16) | lo;
}

// ---------------------------------------------------------------------------
// Kernel 1 (fused): blocks [0, T_ROWS) do target prep; [T_ROWS, +S_ROWS) src prep
// ---------------------------------------------------------------------------
__global__ void prep_kernel(const float* __restrict__ Bt, const float* __restrict__ A) {
    const int b = blockIdx.x, tid = threadIdx.x;
    if (b < T_ROWS) {
        const float4* row = reinterpret_cast<const float4*>(Bt + (size_t)b * DDIM);
        float4 v0 = row[tid * 2], v1 = row[tid * 2 + 1];
        float s = v0.x * v0.x + v0.y * v0.y + v0.z * v0.z + v0.w * v0.w +
                  v1.x * v1.x + v1.y * v1.y + v1.z * v1.z + v1.w * v1.w;
#pragma unroll
        for (int o = 16; o > 0; o >>= 1) s += __shfl_down_sync(0xffffffffu, s, o);
        __shared__ float ws[4];
        __shared__ float s_inv;
        int lane = tid & 31, w = tid >> 5;
        if (lane == 0) ws[w] = s;
        __syncthreads();
        if (tid == 0) {
            float inv = 1.f / fmaxf(sqrtf(ws[0] + ws[1] + ws[2] + ws[3]), 1e-8f);
            g_invn[b] = inv;
            s_inv = inv;
        }
        __syncthreads();
        const float q = s_inv * 64.f;
        uint2 o8;
        o8.x = pack_e4m3x4(v0.x * q, v0.y * q, v0.z * q, v0.w * q);
        o8.y = pack_e4m3x4(v1.x * q, v1.y * q, v1.z * q, v1.w * q);
        *reinterpret_cast<uint2*>(g_tgt8 + (size_t)b * DDIM + tid * 8) = o8;
    } else {
        const int t = b - T_ROWS;
        const float4* row = reinterpret_cast<const float4*>(A + (size_t)t * DDIM);
        float4 v0 = row[tid * 2], v1 = row[tid * 2 + 1];
        uint2 o8;
        o8.x = pack_e4m3x4(v0.x * 4.f, v0.y * 4.f, v0.z * 4.f, v0.w * 4.f);
        o8.y = pack_e4m3x4(v1.x * 4.f, v1.y * 4.f, v1.z * 4.f, v1.w * 4.f);
        *reinterpret_cast<uint2*>(g_src8 + (size_t)t * DDIM + tid * 8) = o8;
    }
}

// ---------------------------------------------------------------------------
// Kernel 2: coarse e4m3 GEMM (128x128 per CTA, warp tile 32x64, K=1024)
//           + fused per-row top-4 (2 threads/row, float4 scan, shfl merge)
// ---------------------------------------------------------------------------
__global__ __launch_bounds__(256, 2)
void coarse_gemm_topk() {
    extern __shared__ char smem[];
    const uint32_t sb = smem_to_u32(smem);
    const int tid = threadIdx.x;
    const int lane = tid & 31;
    const int w = tid >> 5;
    const int wm = w >> 1;          // 0..3
    const int wn = w & 1;           // 0..1
    const int m0 = blockIdx.x * BM;
    const int n0 = blockIdx.y * BN;

    const int lrow = tid >> 1;                  // 0..127
    const int lc0  = (tid & 1) << 2;            // 0 or 4
    const uint8_t* Ag = g_src8 + (size_t)(m0 + lrow) * DDIM + lc0 * 16;
    const int tr = n0 + lrow;
    const uint8_t* Bg = g_tgt8 + (size_t)min(tr, T_ROWS - 1) * DDIM + lc0 * 16;
    const uint32_t bsz = (tr < T_ROWS) ? 16u : 0u;
    uint32_t awoff[4], bwoff[4];
#pragma unroll
    for (int i = 0; i < 4; ++i) {
        int c = lc0 + i;
        awoff[i] = (uint32_t)(lrow * 128 + ((c ^ (lrow & 7)) << 4));
        bwoff[i] = (uint32_t)(BM * 128 + lrow * 128 + ((c ^ (lrow & 7)) << 4));
    }

    float acc[2][8][4];
#pragma unroll
    for (int mi = 0; mi < 2; ++mi)
#pragma unroll
        for (int ni = 0; ni < 8; ++ni)
#pragma unroll
            for (int q = 0; q < 4; ++q) acc[mi][ni][q] = 0.f;

    const int lrow8 = (lane & 7) + ((lane >> 3) & 1) * 8;
    const int khalf = (lane >> 4) & 1;
    int arowA[2], browB[4];
#pragma unroll
    for (int mi = 0; mi < 2; ++mi) arowA[mi] = wm * 32 + mi * 16 + lrow8;
#pragma unroll
    for (int nj = 0; nj < 4; ++nj) browB[nj] = wn * 64 + nj * 16 + lrow8;

#pragma unroll
    for (int s = 0; s < 2; ++s) {
        const uint32_t bbuf = sb + s * STAGE_BYTES;
#pragma unroll
        for (int i = 0; i < 4; ++i) {
            cp_async16(bbuf + awoff[i], Ag + s * BKS + i * 16, 16u);
            cp_async16(bbuf + bwoff[i], Bg + s * BKS + i * 16, bsz);
        }
        cp_commit();
    }

#pragma unroll 1
    for (int s = 0; s < NSTG; ++s) {
        if (s + 2 < NSTG) {
            const uint32_t nb = sb + ((s + 2) % 3) * STAGE_BYTES;
            const int ko = (s + 2) * BKS;
#pragma unroll
            for (int i = 0; i < 4; ++i) {
                cp_async16(nb + awoff[i], Ag + ko + i * 16, 16u);
                cp_async16(nb + bwoff[i], Bg + ko + i * 16, bsz);
            }
        }
        cp_commit();
        cp_wait<2>();
        __syncthreads();

        const uint32_t ab = sb + (s % 3) * STAGE_BYTES;
        const uint32_t bb = ab + BM * 128;
#pragma unroll
        for (int kk = 0; kk < 4; ++kk) {
            const int kc = kk * 2 + khalf;
            uint32_t a[2][4];
#pragma unroll
            for (int mi = 0; mi < 2; ++mi) {
                int r = arowA[mi];
                ldsm_x4(ab + r * 128 + ((kc ^ (r & 7)) << 4),
                        a[mi][0], a[mi][1], a[mi][2], a[mi][3]);
            }
#pragma unroll
            for (int nj = 0; nj < 4; ++nj) {
                int r = browB[nj];
                uint32_t b0, b1, b2, b3;
                ldsm_x4(bb + r * 128 + ((kc ^ (r & 7)) << 4), b0, b1, b2, b3);
#pragma unroll
                for (int mi = 0; mi < 2; ++mi) {
                    mma_fp8(acc[mi][nj * 2][0], acc[mi][nj * 2][1],
                            acc[mi][nj * 2][2], acc[mi][nj * 2][3],
                            a[mi][0], a[mi][1], a[mi][2], a[mi][3], b0, b2);
                    mma_fp8(acc[mi][nj * 2 + 1][0], acc[mi][nj * 2 + 1][1],
                            acc[mi][nj * 2 + 1][2], acc[mi][nj * 2 + 1][3],
                            a[mi][0], a[mi][1], a[mi][2], a[mi][3], b1, b3);
                }
            }
        }
        __syncthreads();
    }

    // ---- epilogue: fragments -> smem sims [128][132]
    float* sims = reinterpret_cast<float*>(smem);
#pragma unroll
    for (int mi = 0; mi < 2; ++mi) {
        const int r = wm * 32 + mi * 16 + (lane >> 2);
#pragma unroll
        for (int ni = 0; ni < 8; ++ni) {
            const int c = wn * 64 + ni * 8 + (lane & 3) * 2;
            *reinterpret_cast<float2*>(sims + r * 132 + c) =
                make_float2(acc[mi][ni][0], acc[mi][ni][1]);
            *reinterpret_cast<float2*>(sims + (r + 8) * 132 + c) =
                make_float2(acc[mi][ni][2], acc[mi][ni][3]);
        }
    }
    __syncthreads();

    // per-row top-4: 2 threads/row, float4 vectorized scan, snapshot shfl merge
    {
        const int row  = tid >> 1;
        const int half = tid & 1;
        const int nmax = min(BN, T_ROWS - n0);   // multiple of 4 (80 on last tile)
        float tv[KNN] = {-FLT_MAX, -FLT_MAX, -FLT_MAX, -FLT_MAX};
        int   ti4[KNN] = {0x7fffffff, 0x7fffffff, 0x7fffffff, 0x7fffffff};
        const float* rowp = sims + row * 132;
        const int c0 = half * 64;
        const int c1 = min(c0 + 64, nmax);
        for (int c = c0; c < c1; c += 4) {
            const float4 v = *reinterpret_cast<const float4*>(rowp + c);
            insL<KNN>(v.x, n0 + c,     tv, ti4);
            insL<KNN>(v.y, n0 + c + 1, tv, ti4);
            insL<KNN>(v.z, n0 + c + 2, tv, ti4);
            insL<KNN>(v.w, n0 + c + 3, tv, ti4);
        }
        // snapshot partner's ORIGINAL list, then insert
        float pv[KNN]; int pi[KNN];
#pragma unroll
        for (int q = 0; q < KNN; ++q) {
            pv[q] = __shfl_xor_sync(0xffffffffu, tv[q], 1);
            pi[q] = __shfl_xor_sync(0xffffffffu, ti4[q], 1);
        }
#pragma unroll
        for (int q = 0; q < KNN; ++q) insL<KNN>(pv[q], pi[q], tv, ti4);
        if (half == 0) {
            const int m = m0 + row;
            const int base = (m * NT + blockIdx.y) * KNN;
#pragma unroll
            for (int q = 0; q < KNN; ++q)
                g_pc[base + q] = make_float2(tv[q], __int_as_float(ti4[q]));
        }
    }
}

// ---------------------------------------------------------------------------
// Kernel 3 (R15 merge, verbatim): merge -> coarse top-12 (serial phase 2)
//           -> block-wide EXACT fp32 rescore -> top-4 -> mean
// ---------------------------------------------------------------------------
__global__ __launch_bounds__(256)
void merge_rescore_kernel(const float* __restrict__ A, const float* __restrict__ Bt,
                          float* __restrict__ out) {
    const int s = blockIdx.x;
    const int tid = threadIdx.x;
    const int lane = tid & 31, warp = tid >> 5;
    const int C = NT * KNN;   // 1564

    __shared__ float sv[256 * KNN];
    __shared__ int   si[256 * KNN];
    __shared__ int   fiR[RESC];
    __shared__ float wsum[RESC * 8];
    __shared__ int   fidx[KNN];

    // phase 1: per-thread strided top-4 (packed float2 loads)
    {
        float tv[KNN] = {-FLT_MAX, -FLT_MAX, -FLT_MAX, -FLT_MAX};
        int   ti4[KNN] = {0x7fffffff, 0x7fffffff, 0x7fffffff, 0x7fffffff};
        const int base = s * C;
        for (int c = tid; c < C; c += 256) {
            const float2 pc = g_pc[base + c];
            insL<KNN>(pc.x, __float_as_int(pc.y), tv, ti4);
        }
#pragma unroll
        for (int q = 0; q < KNN; ++q) { sv[tid * KNN + q] = tv[q]; si[tid * KNN + q] = ti4[q]; }
    }
    __syncthreads();

    // phase 2: single-thread merge -> coarse top-RESC
    if (tid == 0) {
        float fv[RESC]; int fii[RESC];
#pragma unroll
        for (int q = 0; q < RESC; ++q) { fv[q] = -FLT_MAX; fii[q] = 0x7fffffff; }
        for (int c = 0; c < 256 * KNN; ++c) insL<RESC>(sv[c], si[c], fv, fii);
#pragma unroll
        for (int q = 0; q < RESC; ++q) fiR[q] = fii[q];
    }
    __syncthreads();

    // phase 3: block-wide EXACT fp32 rescore of RESC candidates
    const float4 sval = reinterpret_cast<const float4*>(A + (size_t)s * DDIM)[tid];
#pragma unroll 1
    for (int q = 0; q < RESC; ++q) {
        const int idx = fiR[q];
        const float4 t4 = reinterpret_cast<const float4*>(Bt + (size_t)idx * DDIM)[tid];
        float p = sval.x * t4.x + sval.y * t4.y + sval.z * t4.z + sval.w * t4.w;
#pragma unroll
        for (int o = 16; o > 0; o >>= 1) p += __shfl_down_sync(0xffffffffu, p, o);
        if (lane == 0) wsum[q * 8 + warp] = p;
    }
    __syncthreads();

    // phase 4: final exact top-4
    if (tid == 0) {
        float fv[KNN] = {-FLT_MAX, -FLT_MAX, -FLT_MAX, -FLT_MAX};
        int   fii[KNN] = {0x7fffffff, 0x7fffffff, 0x7fffffff, 0x7fffffff};
#pragma unroll
        for (int q = 0; q < RESC; ++q) {
            const int idx = fiR[q];
            float tot = 0.f;
#pragma unroll
            for (int ww = 0; ww < 8; ++ww) tot += wsum[q * 8 + ww];
            insL<KNN>(tot * g_invn[idx], idx, fv, fii);
        }
#pragma unroll
        for (int q = 0; q < KNN; ++q) fidx[q] = fii[q];
    }
    __syncthreads();

    // phase 5: gather 4 fp32 target rows, mean
    const float4 a = reinterpret_cast<const float4*>(Bt + (size_t)fidx[0] * DDIM)[tid];
    const float4 b = reinterpret_cast<const float4*>(Bt + (size_t)fidx[1] * DDIM)[tid];
    const float4 c = reinterpret_cast<const float4*>(Bt + (size_t)fidx[2] * DDIM)[tid];
    const float4 d = reinterpret_cast<const float4*>(Bt + (size_t)fidx[3] * DDIM)[tid];
    float4 r;
    r.x = (a.x + b.x + c.x + d.x) * 0.25f;
    r.y = (a.y + b.y + c.y + d.y) * 0.25f;
    r.z = (a.z + b.z + c.z + d.z) * 0.25f;
    r.w = (a.w + b.w + c.w + d.w) * 0.25f;
    reinterpret_cast<float4*>(out + (size_t)s * DDIM)[tid] = r;
}

// ---------------------------------------------------------------------------
extern "C" void kernel_launch(void* const* d_in, const int* in_sizes, int n_in,
                              void* d_out, int out_size) {
    const float* src = (const float*)d_in[0];   // [2048, 1024]
    const float* tgt = (const float*)d_in[1];   // [50000, 1024]
    float* out = (float*)d_out;                 // [2048, 1024]

    cudaFuncSetAttribute(coarse_gemm_topk,
                         cudaFuncAttributeMaxDynamicSharedMemorySize, SMEM_BYTES);

    prep_kernel<<<T_ROWS + S_ROWS, 128>>>(tgt, src);
    coarse_gemm_topk<<<dim3(MT, NT), 256, SMEM_BYTES>>>();
    merge_rescore_kernel<<<S_ROWS, 256>>>(src, tgt, out);
}